// round 8
// baseline (speedup 1.0000x reference)
#include <cuda_runtime.h>
#include <math.h>

#define BB   4
#define NPTS 4096
#define KNN  16
#define CIN  61
#define INF  64
#define OUTF 128
#define NROW (BB*NPTS)          // 16384
#define NITEM (NROW*KNN)        // 262144

typedef unsigned long long u64;
typedef unsigned int       u32;

// ------------------- device scratch (no allocations allowed) ----------------
__device__ int   g_idx[NITEM];
__device__ float g_feat1[NROW*INF];
__device__ float g_lin1[NROW*OUTF];
__device__ float g_lin2[NROW*OUTF];
__device__ float g_part[2*512*256];
__device__ float g_bn[2*2*OUTF];

// ---------------- packed fp32x2 helpers (FFMA2 pipe) ------------------------
__device__ __forceinline__ u64 pk2(float a) {
    u64 r; asm("mov.b64 %0,{%1,%1};" : "=l"(r) : "f"(a)); return r;
}
__device__ __forceinline__ u64 pk(float lo, float hi) {
    u64 r; asm("mov.b64 %0,{%1,%2};" : "=l"(r) : "f"(lo), "f"(hi)); return r;
}
__device__ __forceinline__ u64 fma2(u64 a, u64 b, u64 c) {
    u64 d; asm("fma.rn.f32x2 %0,%1,%2,%3;" : "=l"(d) : "l"(a), "l"(b), "l"(c)); return d;
}
__device__ __forceinline__ float2 upk(u64 v) {
    float2 f; asm("mov.b64 {%0,%1},%2;" : "=f"(f.x), "=f"(f.y) : "l"(v)); return f;
}

// ----------------------- profiling alignment nop ----------------------------
__global__ void nop_kernel() {}

// ============ K1: exact KNN v5 — register keys + bisection probes ===========
// 1024 blocks x 512 threads; block handles 16 queries of one batch as 8 pairs.
// Per pair: one shared distance sweep (keys in regs), 11 barrier-reduction
// probes find the 16th-NN bin (top-11 float bits, monotone for d2>=0), tiny
// boundary-bin compaction + exact (d2,index) rank select.
__global__ __launch_bounds__(512, 2) void knn_kernel(const float* __restrict__ pos) {
    extern __shared__ float sm[];
    float* sp = sm;                                  // [NPTS*3]
    u32*  warpsum = (u32*)(sm + NPTS*3);             // [2][16] parity-buffered
    u32*  listva  = warpsum + 32;                    // [256]
    int*  listja  = (int*)(listva + 256);            // [256]
    u32*  listvb  = (u32*)(listja + 256);            // [256]
    int*  listjb  = (int*)(listvb + 256);            // [256]
    int*  outja   = listjb + 256;                    // [16]
    int*  outjb   = outja + 16;                      // [16]
    int*  ctl     = outjb + 16;                      // [4]

    const int tid  = threadIdx.x;
    const int lane = tid & 31;
    const int wid  = tid >> 5;
    const int b    = blockIdx.x >> 8;                // 256 blocks per batch
    const int q0   = (blockIdx.x & 255) << 4;        // 16 queries per block
    const float* pb = pos + (size_t)b * NPTS * 3;

    for (int i = tid; i < NPTS*3; i += 512) sp[i] = pb[i];
    __syncthreads();

    for (int qp = 0; qp < 8; qp++) {
        const int qa = q0 + 2*qp, qb = qa + 1;
        if (tid == 0) { ctl[0] = 0; ctl[1] = 0; ctl[2] = 0; ctl[3] = 0; }

        const float ax = sp[3*qa], ay = sp[3*qa+1], az = sp[3*qa+2];
        const float bx = sp[3*qb], by = sp[3*qb+1], bz = sp[3*qb+2];

        // distance sweep: 8 candidates per thread, both queries share pos LDS
        u32 kka[8], kkb[8];
#pragma unroll
        for (int t = 0; t < 8; t++) {
            const int j = tid + 512*t;
            const float px = sp[3*j], py = sp[3*j+1], pz = sp[3*j+2];
            const float dax = ax - px, day = ay - py, daz = az - pz;
            const float dbx = bx - px, dby = by - py, dbz = bz - pz;
            // match XLA rounding: no fma contraction, left-to-right sum
            kka[t] = __float_as_uint(__fadd_rn(__fadd_rn(__fmul_rn(dax,dax),
                         __fmul_rn(day,day)), __fmul_rn(daz,daz)));
            kkb[t] = __float_as_uint(__fadd_rn(__fadd_rn(__fmul_rn(dbx,dbx),
                         __fmul_rn(dby,dby)), __fmul_rn(dbz,dbz)));
        }

        // bisection on 11-bit bins; invariant cnt(<lo)<16 <= cnt(<hi)
        int loa = 0, hia = 2048, cla = 0;
        int lob = 0, hib = 2048, clb = 0;
#pragma unroll 1
        for (int it = 0; it < 11; it++) {
            const int mida = (loa + hia) >> 1;
            const int midb = (lob + hib) >> 1;
            int ca = 0, cb = 0;
#pragma unroll
            for (int t = 0; t < 8; t++) {
                ca += (kka[t] >> 21) < (u32)mida;
                cb += (kkb[t] >> 21) < (u32)midb;
            }
            u32 packed = (u32)ca | ((u32)cb << 16);
            packed = __reduce_add_sync(0xffffffffu, packed);
            if (lane == 0) warpsum[(it & 1)*16 + wid] = packed;
            __syncthreads();
            u32 tot = 0;
            const uint4* wsv = (const uint4*)(warpsum + (it & 1)*16);
#pragma unroll
            for (int w = 0; w < 4; w++) {
                const uint4 v4 = wsv[w];
                tot += (v4.x + v4.y) + (v4.z + v4.w);
            }
            const int ta = (int)(tot & 0xFFFFu), tb = (int)(tot >> 16);
            if (ta >= 16) hia = mida; else { loa = mida; cla = ta; }
            if (tb >= 16) hib = midb; else { lob = midb; clb = tb; }
        }
        const u32 bsa = (u32)loa, bsb = (u32)lob;   // boundary bins; cla/clb = #strictly below

        // compact: below-bin -> definitely in top-16; boundary-bin -> list
#pragma unroll
        for (int t = 0; t < 8; t++) {
            const int j = tid + 512*t;
            const u32 ba = kka[t] >> 21;
            if (ba < bsa)       { const int p = atomicAdd(&ctl[0], 1); outja[p] = j; }
            else if (ba == bsa) { const int p = atomicAdd(&ctl[1], 1);
                                  if (p < 256) { listva[p] = kka[t]; listja[p] = j; } }
            const u32 bb = kkb[t] >> 21;
            if (bb < bsb)       { const int p = atomicAdd(&ctl[2], 1); outjb[p] = j; }
            else if (bb == bsb) { const int p = atomicAdd(&ctl[3], 1);
                                  if (p < 256) { listvb[p] = kkb[t]; listjb[p] = j; } }
        }
        __syncthreads();

        // exact (d2, index) lexicographic rank select inside the boundary bin
        const int cnta = min(ctl[1], 256), needa = 16 - cla;
        if (tid < cnta) {
            const u64 me = ((u64)listva[tid] << 32) | (u32)listja[tid];
            int rank = 0;
            for (int i = 0; i < cnta; i++)
                rank += ((((u64)listva[i] << 32) | (u32)listja[i]) < me);
            if (rank < needa) outja[cla + rank] = listja[tid];
        }
        const int cntb = min(ctl[3], 256), needb = 16 - clb;
        if (tid < cntb) {
            const u64 me = ((u64)listvb[tid] << 32) | (u32)listjb[tid];
            int rank = 0;
            for (int i = 0; i < cntb; i++)
                rank += ((((u64)listvb[i] << 32) | (u32)listjb[i]) < me);
            if (rank < needb) outjb[clb + rank] = listjb[tid];
        }
        __syncthreads();
        if (tid < 16)      g_idx[((b*NPTS + qa) << 4) + tid]        = outja[tid];
        else if (tid < 32) g_idx[((b*NPTS + qb) << 4) + (tid - 16)] = outjb[tid - 16];
        __syncthreads();
    }
}

// ============ K2: per-neighbor MLP + weighted max-pool (FFMA2) ==============
__global__ __launch_bounds__(128) void relconv_kernel(
    const float* __restrict__ x, const float* __restrict__ pos,
    const float* __restrict__ rw1, const float* __restrict__ rb1,
    const float* __restrict__ rw2, const float* __restrict__ rb2,
    const float* __restrict__ rw3, const float* __restrict__ rb3) {

    __shared__ __align__(16) float sw1[10*32];
    __shared__ __align__(16) float sb1[32];
    __shared__ __align__(16) float sw2[32*64];
    __shared__ __align__(16) float sb2[64];
    __shared__ __align__(16) float sw3[64*64];
    __shared__ __align__(16) float sb3[64];

    const int tid = threadIdx.x;
    for (int i = tid; i < 320;  i += 128) sw1[i] = rw1[i];
    for (int i = tid; i < 32;   i += 128) sb1[i] = rb1[i];
    for (int i = tid; i < 2048; i += 128) sw2[i] = rw2[i];
    for (int i = tid; i < 64;   i += 128) sb2[i] = rb2[i];
    for (int i = tid; i < 4096; i += 128) sw3[i] = rw3[i];
    for (int i = tid; i < 64;   i += 128) sb3[i] = rb3[i];
    __syncthreads();

    const int item = blockIdx.x * 128 + tid;
    const int k = item & (KNN-1);
    const int n = (item >> 4) & (NPTS-1);
    const int b = item >> 16;
    const int j = g_idx[item];

    const float* pb = pos + (size_t)b * NPTS * 3;
    const float cx = pb[3*n], cy = pb[3*n+1], cz = pb[3*n+2];
    const float gx = pb[3*j], gy = pb[3*j+1], gz = pb[3*j+2];
    const float rx = gx - cx, ry = gy - cy, rz = gz - cz;
    const float s2 = rx*rx + ry*ry + rz*rz;
    const float dis = (s2 > 0.f) ? sqrtf(s2) : 0.f;

    const float f[10] = {cx, cy, cz, gx, gy, gz, rx, ry, rz, dis};

    const ulonglong2* w1q = (const ulonglong2*)sw1;
    const ulonglong2* w2q = (const ulonglong2*)sw2;
    const ulonglong2* w3q = (const ulonglong2*)sw3;

    // layer1: 10 -> 32, relu
    u64 h1p[16];
#pragma unroll
    for (int d = 0; d < 16; d++) h1p[d] = ((const u64*)sb1)[d];
#pragma unroll
    for (int c = 0; c < 10; c++) {
        const u64 aa = pk2(f[c]);
#pragma unroll
        for (int dq = 0; dq < 8; dq++) {
            const ulonglong2 ww = w1q[c*8 + dq];
            h1p[2*dq]   = fma2(aa, ww.x, h1p[2*dq]);
            h1p[2*dq+1] = fma2(aa, ww.y, h1p[2*dq+1]);
        }
    }
    float h1[32];
#pragma unroll
    for (int d = 0; d < 16; d++) {
        float2 t = upk(h1p[d]);
        h1[2*d]   = fmaxf(t.x, 0.f);
        h1[2*d+1] = fmaxf(t.y, 0.f);
    }

    // layer2: 32 -> 64, relu
    u64 h2p[32];
#pragma unroll
    for (int d = 0; d < 32; d++) h2p[d] = ((const u64*)sb2)[d];
#pragma unroll
    for (int c = 0; c < 32; c++) {
        const u64 aa = pk2(h1[c]);
#pragma unroll
        for (int dq = 0; dq < 16; dq++) {
            const ulonglong2 ww = w2q[c*16 + dq];
            h2p[2*dq]   = fma2(aa, ww.x, h2p[2*dq]);
            h2p[2*dq+1] = fma2(aa, ww.y, h2p[2*dq+1]);
        }
    }
    float h2[64];
#pragma unroll
    for (int d = 0; d < 32; d++) {
        float2 t = upk(h2p[d]);
        h2[2*d]   = fmaxf(t.x, 0.f);
        h2[2*d+1] = fmaxf(t.y, 0.f);
    }

    // layer3: 64 -> 64, no relu
    u64 wp[32];
#pragma unroll
    for (int d = 0; d < 32; d++) wp[d] = ((const u64*)sb3)[d];
#pragma unroll
    for (int c = 0; c < 64; c++) {
        const u64 aa = pk2(h2[c]);
#pragma unroll
        for (int dq = 0; dq < 16; dq++) {
            const ulonglong2 ww = w3q[c*16 + dq];
            wp[2*dq]   = fma2(aa, ww.x, wp[2*dq]);
            wp[2*dq+1] = fma2(aa, ww.y, wp[2*dq+1]);
        }
    }

    // weights * feat, warp max over k (16 lanes), relu, store (k==0 lane)
    const float* xr = x + ((size_t)b * NPTS + j) * CIN;
    float* outp = g_feat1 + ((size_t)b * NPTS + n) * INF;
#pragma unroll
    for (int d = 0; d < 32; d++) {
        const float2 t = upk(wp[d]);
        const int ch0 = 2*d, ch1 = 2*d + 1;
        float f0, f1;
        if (ch0 < CIN)       f0 = xr[ch0];
        else if (ch0 == 62)  f0 = gy;
        else                 f0 = gx;
        if (ch1 < CIN)       f1 = xr[ch1];
        else if (ch1 == 61)  f1 = gx;
        else                 f1 = gz;
        float v0 = t.x * f0;
        float v1 = t.y * f1;
#pragma unroll
        for (int off = 8; off >= 1; off >>= 1) {
            v0 = fmaxf(v0, __shfl_xor_sync(0xffffffffu, v0, off));
            v1 = fmaxf(v1, __shfl_xor_sync(0xffffffffu, v1, off));
        }
        if (k == 0) {
            outp[ch0] = fmaxf(v0, 0.f);
            outp[ch1] = fmaxf(v1, 0.f);
        }
    }
}

// ======== K3: GEMM1 [16384,64]@[64,128] + fb1, fused col-stats ==============
__global__ __launch_bounds__(256) void gemm1_kernel(
    const float* __restrict__ fw1, const float* __restrict__ fb1) {
    extern __shared__ float dyn[];
    float* sW    = dyn;                 // 64*128
    float* sAT   = dyn + 8192;          // 64*36
    float* sred  = dyn + 8192 + 2304;   // 8*128
    float* sqred = sred + 1024;
    const int tid = threadIdx.x;
    const int r0  = blockIdx.x * 32;

    for (int i = tid; i < 2048; i += 256)
        ((float4*)sW)[i] = ((const float4*)fw1)[i];
    for (int i = tid; i < 32*64; i += 256) {
        const int r = i >> 6, c = i & 63;
        sAT[c*36 + r] = g_feat1[(size_t)(r0 + r) * INF + c];
    }
    __syncthreads();

    const int cg = tid & 31;
    const int rg = tid >> 5;
    const float4 fb = reinterpret_cast<const float4*>(fb1)[cg];
    u64 accp[4][2];
#pragma unroll
    for (int i = 0; i < 4; i++) { accp[i][0] = pk(fb.x, fb.y); accp[i][1] = pk(fb.z, fb.w); }

    const ulonglong2* sWq = (const ulonglong2*)sW;
#pragma unroll 4
    for (int kk = 0; kk < 64; kk++) {
        const float4 a = *reinterpret_cast<const float4*>(&sAT[kk*36 + 4*rg]);
        const ulonglong2 ww = sWq[kk*32 + cg];
        const float av[4] = {a.x, a.y, a.z, a.w};
#pragma unroll
        for (int i = 0; i < 4; i++) {
            const u64 aa = pk2(av[i]);
            accp[i][0] = fma2(aa, ww.x, accp[i][0]);
            accp[i][1] = fma2(aa, ww.y, accp[i][1]);
        }
    }
    float s[4] = {0,0,0,0}, sq[4] = {0,0,0,0};
#pragma unroll
    for (int i = 0; i < 4; i++) {
        const float2 lo = upk(accp[i][0]), hi = upk(accp[i][1]);
        float4 o = make_float4(lo.x, lo.y, hi.x, hi.y);
        *reinterpret_cast<float4*>(&g_lin1[(size_t)(r0 + 4*rg + i) * OUTF + 4*cg]) = o;
        s[0] += o.x; s[1] += o.y; s[2] += o.z; s[3] += o.w;
        sq[0] = fmaf(o.x,o.x,sq[0]); sq[1] = fmaf(o.y,o.y,sq[1]);
        sq[2] = fmaf(o.z,o.z,sq[2]); sq[3] = fmaf(o.w,o.w,sq[3]);
    }
#pragma unroll
    for (int qq = 0; qq < 4; qq++) { sred[rg*128 + 4*cg + qq] = s[qq]; sqred[rg*128 + 4*cg + qq] = sq[qq]; }
    __syncthreads();
    if (tid < 128) {
        float a = 0.f, v = 0.f;
#pragma unroll
        for (int r = 0; r < 8; r++) { a += sred[r*128 + tid]; v += sqred[r*128 + tid]; }
        g_part[blockIdx.x*256 + tid]       = a;
        g_part[blockIdx.x*256 + 128 + tid] = v;
    }
}

// ==== K4: GEMM2 with BN1+relu on load, [16384,128]@[128,128]+fb2, stats =====
__global__ __launch_bounds__(256) void gemm2_kernel(
    const float* __restrict__ fw2, const float* __restrict__ fb2) {
    extern __shared__ float dyn[];
    float* sW    = dyn;                  // 128*128
    float* sAT   = dyn + 16384;          // 128*36
    float* sred  = dyn + 16384 + 4608;   // 8*128
    float* sqred = sred + 1024;
    const int tid = threadIdx.x;
    const int r0  = blockIdx.x * 32;

    for (int i = tid; i < 4096; i += 256)
        ((float4*)sW)[i] = ((const float4*)fw2)[i];
    const float* bn = g_bn;       // stage 0
    for (int i = tid; i < 32*128; i += 256) {
        const int r = i >> 7, c = i & 127;
        float v = g_lin1[(size_t)(r0 + r) * OUTF + c];
        v = fmaf(v, bn[c], bn[128 + c]);
        sAT[c*36 + r] = fmaxf(v, 0.f);
    }
    __syncthreads();

    const int cg = tid & 31;
    const int rg = tid >> 5;
    const float4 fb = reinterpret_cast<const float4*>(fb2)[cg];
    u64 accp[4][2];
#pragma unroll
    for (int i = 0; i < 4; i++) { accp[i][0] = pk(fb.x, fb.y); accp[i][1] = pk(fb.z, fb.w); }

    const ulonglong2* sWq = (const ulonglong2*)sW;
#pragma unroll 4
    for (int kk = 0; kk < 128; kk++) {
        const float4 a = *reinterpret_cast<const float4*>(&sAT[kk*36 + 4*rg]);
        const ulonglong2 ww = sWq[kk*32 + cg];
        const float av[4] = {a.x, a.y, a.z, a.w};
#pragma unroll
        for (int i = 0; i < 4; i++) {
            const u64 aa = pk2(av[i]);
            accp[i][0] = fma2(aa, ww.x, accp[i][0]);
            accp[i][1] = fma2(aa, ww.y, accp[i][1]);
        }
    }
    float s[4] = {0,0,0,0}, sq[4] = {0,0,0,0};
#pragma unroll
    for (int i = 0; i < 4; i++) {
        const float2 lo = upk(accp[i][0]), hi = upk(accp[i][1]);
        float4 o = make_float4(lo.x, lo.y, hi.x, hi.y);
        *reinterpret_cast<float4*>(&g_lin2[(size_t)(r0 + 4*rg + i) * OUTF + 4*cg]) = o;
        s[0] += o.x; s[1] += o.y; s[2] += o.z; s[3] += o.w;
        sq[0] = fmaf(o.x,o.x,sq[0]); sq[1] = fmaf(o.y,o.y,sq[1]);
        sq[2] = fmaf(o.z,o.z,sq[2]); sq[3] = fmaf(o.w,o.w,sq[3]);
    }
#pragma unroll
    for (int qq = 0; qq < 4; qq++) { sred[rg*128 + 4*cg + qq] = s[qq]; sqred[rg*128 + 4*cg + qq] = sq[qq]; }
    __syncthreads();
    if (tid < 128) {
        float a = 0.f, v = 0.f;
#pragma unroll
        for (int r = 0; r < 8; r++) { a += sred[r*128 + tid]; v += sqred[r*128 + tid]; }
        g_part[512*256 + blockIdx.x*256 + tid]       = a;
        g_part[512*256 + blockIdx.x*256 + 128 + tid] = v;
    }
}

// ======== finalize BN coefficients (parallelized: 1024 threads) =============
__global__ __launch_bounds__(1024) void finstats_kernel(
    int sel, const float* __restrict__ gamma, const float* __restrict__ beta) {
    __shared__ float red[4*256];
    __shared__ float tot[256];
    const float* part = g_part + sel * (512*256);
    float* bn = g_bn + sel * (2*OUTF);
    const int t = threadIdx.x;
    const int c = t & 255;
    const int g = t >> 8;
    float s = 0.f;
    const int rbeg = g * 128;
#pragma unroll 4
    for (int i = 0; i < 128; i++) s += part[(rbeg + i)*256 + c];
    red[g*256 + c] = s;
    __syncthreads();
    if (t < 256) tot[t] = (red[t] + red[256 + t]) + (red[512 + t] + red[768 + t]);
    __syncthreads();
    if (t < 128) {
        const float inv_n = 1.f / (float)NROW;
        const float m  = tot[t] * inv_n;
        const float v  = tot[128 + t] * inv_n - m * m;
        const float rs = rsqrtf(v + 1e-5f);
        const float a  = rs * gamma[t];
        bn[t]       = a;
        bn[128 + t] = beta[t] - m * a;
    }
}

// ===================== K7: final BN2 -> output (vectorized) =================
__global__ __launch_bounds__(1024) void final_kernel(float* __restrict__ out) {
    const int i = blockIdx.x * 1024 + threadIdx.x;   // float4 units
    const int c0 = (i << 2) & 127;
    const float* bn = g_bn + 2*OUTF;
    const float4 v = ((const float4*)g_lin2)[i];
    float4 o;
    o.x = fmaf(v.x, bn[c0],   bn[128 + c0]);
    o.y = fmaf(v.y, bn[c0+1], bn[128 + c0 + 1]);
    o.z = fmaf(v.z, bn[c0+2], bn[128 + c0 + 2]);
    o.w = fmaf(v.w, bn[c0+3], bn[128 + c0 + 3]);
    ((float4*)out)[i] = o;
}

// ============================================================================
extern "C" void kernel_launch(void* const* d_in, const int* in_sizes, int n_in,
                              void* d_out, int out_size) {
    (void)in_sizes; (void)n_in; (void)out_size;
    const float* x   = (const float*)d_in[0];
    const float* pos = (const float*)d_in[1];
    const float* rw1 = (const float*)d_in[2];
    const float* rb1 = (const float*)d_in[3];
    const float* rw2 = (const float*)d_in[4];
    const float* rb2 = (const float*)d_in[5];
    const float* rw3 = (const float*)d_in[6];
    const float* rb3 = (const float*)d_in[7];
    const float* fw1 = (const float*)d_in[8];
    const float* fb1 = (const float*)d_in[9];
    const float* g1  = (const float*)d_in[10];
    const float* b1  = (const float*)d_in[11];
    const float* fw2 = (const float*)d_in[12];
    const float* fb2 = (const float*)d_in[13];
    const float* g2  = (const float*)d_in[14];
    const float* b2  = (const float*)d_in[15];
    float* out = (float*)d_out;

    // 3 nops so the ncu capture (4th launch) lands on knn_kernel.
    nop_kernel<<<1, 32>>>();
    nop_kernel<<<1, 32>>>();
    nop_kernel<<<1, 32>>>();

    const int smem_knn = (NPTS*3 + 32 + 4*256 + 32 + 4) * 4;  // ~53.4 KB
    cudaFuncSetAttribute(knn_kernel, cudaFuncAttributeMaxDynamicSharedMemorySize, smem_knn);
    knn_kernel<<<1024, 512, smem_knn>>>(pos);

    relconv_kernel<<<NITEM/128, 128>>>(x, pos, rw1, rb1, rw2, rb2, rw3, rb3);

    const int smem1 = (8192 + 2304 + 2048) * 4;
    cudaFuncSetAttribute(gemm1_kernel, cudaFuncAttributeMaxDynamicSharedMemorySize, smem1);
    gemm1_kernel<<<NROW/32, 256, smem1>>>(fw1, fb1);
    finstats_kernel<<<1, 1024>>>(0, g1, b1);

    const int smem2 = (16384 + 4608 + 2048) * 4;
    cudaFuncSetAttribute(gemm2_kernel, cudaFuncAttributeMaxDynamicSharedMemorySize, smem2);
    gemm2_kernel<<<NROW/32, 256, smem2>>>(fw2, fb2);
    finstats_kernel<<<1, 1024>>>(1, g2, b2);

    final_kernel<<<524288/1024, 1024>>>(out);
}

// round 9
// speedup vs baseline: 1.2187x; 1.2187x over previous
#include <cuda_runtime.h>
#include <math.h>

#define BB   4
#define NPTS 4096
#define KNN  16
#define CIN  61
#define INF  64
#define OUTF 128
#define NROW (BB*NPTS)          // 16384
#define NITEM (NROW*KNN)        // 262144

typedef unsigned long long u64;
typedef unsigned int       u32;

// ------------------- device scratch (no allocations allowed) ----------------
__device__ int   g_idx[NITEM];
__device__ float g_feat1[NROW*INF];
__device__ float g_lin1[NROW*OUTF];
__device__ float g_lin2[NROW*OUTF];
__device__ float g_part[2*512*256];
__device__ float g_bn[2*2*OUTF];

// ---------------- packed fp32x2 helpers (FFMA2 pipe) ------------------------
__device__ __forceinline__ u64 pk2(float a) {
    u64 r; asm("mov.b64 %0,{%1,%1};" : "=l"(r) : "f"(a)); return r;
}
__device__ __forceinline__ u64 pk(float lo, float hi) {
    u64 r; asm("mov.b64 %0,{%1,%2};" : "=l"(r) : "f"(lo), "f"(hi)); return r;
}
__device__ __forceinline__ u64 fma2(u64 a, u64 b, u64 c) {
    u64 d; asm("fma.rn.f32x2 %0,%1,%2,%3;" : "=l"(d) : "l"(a), "l"(b), "l"(c)); return d;
}
__device__ __forceinline__ float2 upk(u64 v) {
    float2 f; asm("mov.b64 {%0,%1},%2;" : "=f"(f.x), "=f"(f.y) : "l"(v)); return f;
}

// ----------------------- profiling alignment nop ----------------------------
__global__ void nop_kernel() {}

// ===== K1: exact KNN v6 — radix histogram, register-resident candidates =====
// 1024 blocks x 256 threads; block = 16 queries of one batch, sequential.
// Candidate coords (16 per thread, fixed j = tid+256t) loaded to registers
// ONCE and reused across all 16 queries; distance keys stay in registers.
__global__ __launch_bounds__(256, 2) void knn_kernel(const float* __restrict__ pos) {
    extern __shared__ float sm[];
    float* sp    = sm;                        // [NPTS*3]
    u32*   hist  = (u32*)(sm + NPTS*3);       // [2048]
    u32*   swarp = hist + 2048;               // [8]
    u32*   listv = swarp + 8;                 // [512]
    int*   listj = (int*)(listv + 512);       // [512]
    int*   outj  = listj + 512;               // [16]
    int*   ctl   = outj + 16;                 // [4]

    const int tid  = threadIdx.x;
    const int lane = tid & 31;
    const int wid  = tid >> 5;
    const int b    = blockIdx.x >> 8;         // 256 blocks per batch
    const int q0   = (blockIdx.x & 255) << 4; // 16 queries per block
    const float* pb = pos + (size_t)b * NPTS * 3;

    for (int i = tid; i < NPTS*3; i += 256) sp[i] = pb[i];
    __syncthreads();

    // candidate coords -> registers (fixed across all queries of this block)
    float px[16], py[16], pz[16];
#pragma unroll
    for (int t = 0; t < 16; t++) {
        const int j = tid + 256*t;
        px[t] = sp[3*j]; py[t] = sp[3*j+1]; pz[t] = sp[3*j+2];
    }

    for (int qi = 0; qi < 16; qi++) {
        const int q = q0 + qi;
        // clear histogram (512 uint4) + counters
        {
            uint4* h4 = (uint4*)hist;
            const uint4 z = make_uint4(0,0,0,0);
            h4[tid] = z; h4[256 + tid] = z;
        }
        if (tid == 0) { ctl[0] = 0; ctl[1] = 0; }
        __syncthreads();

        const float qx = sp[3*q], qy = sp[3*q+1], qz = sp[3*q+2];

        // distance keys in registers + histogram build
        u32 kk[16];
#pragma unroll
        for (int t = 0; t < 16; t++) {
            const float dx = qx - px[t], dy = qy - py[t], dz = qz - pz[t];
            // match XLA rounding: no fma contraction, left-to-right sum
            kk[t] = __float_as_uint(__fadd_rn(__fadd_rn(__fmul_rn(dx,dx),
                        __fmul_rn(dy,dy)), __fmul_rn(dz,dz)));
            atomicAdd(&hist[kk[t] >> 21], 1u);
        }
        __syncthreads();

        // prefix over 256 chunks of 8 bins: warp shfl scan + cross-warp fixup
        u32 part;
        {
            const uint4* h4 = (const uint4*)hist;
            const uint4 a = h4[2*tid], c = h4[2*tid+1];
            part = (a.x + a.y) + (a.z + a.w) + (c.x + c.y) + (c.z + c.w);
        }
        u32 v = part;
#pragma unroll
        for (int off = 1; off < 32; off <<= 1) {
            u32 nb = __shfl_up_sync(0xffffffffu, v, off);
            if (lane >= off) v += nb;
        }
        if (lane == 31) swarp[wid] = v;
        __syncthreads();
        u32 base = 0;
#pragma unroll
        for (int w = 0; w < 8; w++) base += (w < wid) ? swarp[w] : 0u;
        const u32 incl = base + v, excl = incl - part;
        if (excl < 16u && incl >= 16u) {
            u32 c = excl;
#pragma unroll
            for (int k2 = 0; k2 < 8; k2++) {
                const u32 h = hist[tid*8 + k2];
                if (c < 16u && c + h >= 16u) { ctl[2] = tid*8 + k2; ctl[3] = (int)c; break; }
                c += h;
            }
        }
        __syncthreads();
        const u32 bstar = (u32)ctl[2];
        const int Lb    = ctl[3];

        // classify from register keys: below-bin -> top-16 (set order free);
        // boundary-bin -> candidate list
#pragma unroll
        for (int t = 0; t < 16; t++) {
            const u32 key = kk[t] >> 21;
            if (key < bstar) {
                const int p = atomicAdd(&ctl[0], 1);
                outj[p] = tid + 256*t;
            } else if (key == bstar) {
                const int p = atomicAdd(&ctl[1], 1);
                if (p < 512) { listv[p] = kk[t]; listj[p] = tid + 256*t; }
            }
        }
        __syncthreads();

        // exact (d2, index) lexicographic rank select inside boundary bin
        const int cnt = min(ctl[1], 512), need = 16 - Lb;
        if (tid < cnt) {
            const u64 me = ((u64)listv[tid] << 32) | (u32)listj[tid];
            int rank = 0;
            for (int i = 0; i < cnt; i++)
                rank += ((((u64)listv[i] << 32) | (u32)listj[i]) < me);
            if (rank < need) outj[Lb + rank] = listj[tid];
        }
        __syncthreads();
        if (tid < 16) g_idx[((b*NPTS + q) << 4) + tid] = outj[tid];
        __syncthreads();
    }
}

// ============ K2: per-neighbor MLP + weighted max-pool (FFMA2) ==============
__global__ __launch_bounds__(128) void relconv_kernel(
    const float* __restrict__ x, const float* __restrict__ pos,
    const float* __restrict__ rw1, const float* __restrict__ rb1,
    const float* __restrict__ rw2, const float* __restrict__ rb2,
    const float* __restrict__ rw3, const float* __restrict__ rb3) {

    __shared__ __align__(16) float sw1[10*32];
    __shared__ __align__(16) float sb1[32];
    __shared__ __align__(16) float sw2[32*64];
    __shared__ __align__(16) float sb2[64];
    __shared__ __align__(16) float sw3[64*64];
    __shared__ __align__(16) float sb3[64];

    const int tid = threadIdx.x;
    for (int i = tid; i < 320;  i += 128) sw1[i] = rw1[i];
    for (int i = tid; i < 32;   i += 128) sb1[i] = rb1[i];
    for (int i = tid; i < 2048; i += 128) sw2[i] = rw2[i];
    for (int i = tid; i < 64;   i += 128) sb2[i] = rb2[i];
    for (int i = tid; i < 4096; i += 128) sw3[i] = rw3[i];
    for (int i = tid; i < 64;   i += 128) sb3[i] = rb3[i];
    __syncthreads();

    const int item = blockIdx.x * 128 + tid;
    const int k = item & (KNN-1);
    const int n = (item >> 4) & (NPTS-1);
    const int b = item >> 16;
    const int j = g_idx[item];

    const float* pb = pos + (size_t)b * NPTS * 3;
    const float cx = pb[3*n], cy = pb[3*n+1], cz = pb[3*n+2];
    const float gx = pb[3*j], gy = pb[3*j+1], gz = pb[3*j+2];
    const float rx = gx - cx, ry = gy - cy, rz = gz - cz;
    const float s2 = rx*rx + ry*ry + rz*rz;
    const float dis = (s2 > 0.f) ? sqrtf(s2) : 0.f;

    const float f[10] = {cx, cy, cz, gx, gy, gz, rx, ry, rz, dis};

    const ulonglong2* w1q = (const ulonglong2*)sw1;
    const ulonglong2* w2q = (const ulonglong2*)sw2;
    const ulonglong2* w3q = (const ulonglong2*)sw3;

    // layer1: 10 -> 32, relu
    u64 h1p[16];
#pragma unroll
    for (int d = 0; d < 16; d++) h1p[d] = ((const u64*)sb1)[d];
#pragma unroll
    for (int c = 0; c < 10; c++) {
        const u64 aa = pk2(f[c]);
#pragma unroll
        for (int dq = 0; dq < 8; dq++) {
            const ulonglong2 ww = w1q[c*8 + dq];
            h1p[2*dq]   = fma2(aa, ww.x, h1p[2*dq]);
            h1p[2*dq+1] = fma2(aa, ww.y, h1p[2*dq+1]);
        }
    }
    float h1[32];
#pragma unroll
    for (int d = 0; d < 16; d++) {
        float2 t = upk(h1p[d]);
        h1[2*d]   = fmaxf(t.x, 0.f);
        h1[2*d+1] = fmaxf(t.y, 0.f);
    }

    // layer2: 32 -> 64, relu
    u64 h2p[32];
#pragma unroll
    for (int d = 0; d < 32; d++) h2p[d] = ((const u64*)sb2)[d];
#pragma unroll
    for (int c = 0; c < 32; c++) {
        const u64 aa = pk2(h1[c]);
#pragma unroll
        for (int dq = 0; dq < 16; dq++) {
            const ulonglong2 ww = w2q[c*16 + dq];
            h2p[2*dq]   = fma2(aa, ww.x, h2p[2*dq]);
            h2p[2*dq+1] = fma2(aa, ww.y, h2p[2*dq+1]);
        }
    }
    float h2[64];
#pragma unroll
    for (int d = 0; d < 32; d++) {
        float2 t = upk(h2p[d]);
        h2[2*d]   = fmaxf(t.x, 0.f);
        h2[2*d+1] = fmaxf(t.y, 0.f);
    }

    // layer3: 64 -> 64, no relu
    u64 wp[32];
#pragma unroll
    for (int d = 0; d < 32; d++) wp[d] = ((const u64*)sb3)[d];
#pragma unroll
    for (int c = 0; c < 64; c++) {
        const u64 aa = pk2(h2[c]);
#pragma unroll
        for (int dq = 0; dq < 16; dq++) {
            const ulonglong2 ww = w3q[c*16 + dq];
            wp[2*dq]   = fma2(aa, ww.x, wp[2*dq]);
            wp[2*dq+1] = fma2(aa, ww.y, wp[2*dq+1]);
        }
    }

    // weights * feat, warp max over k (16 lanes), relu, store (k==0 lane)
    const float* xr = x + ((size_t)b * NPTS + j) * CIN;
    float* outp = g_feat1 + ((size_t)b * NPTS + n) * INF;
#pragma unroll
    for (int d = 0; d < 32; d++) {
        const float2 t = upk(wp[d]);
        const int ch0 = 2*d, ch1 = 2*d + 1;
        float f0, f1;
        if (ch0 < CIN)       f0 = xr[ch0];
        else if (ch0 == 62)  f0 = gy;
        else                 f0 = gx;
        if (ch1 < CIN)       f1 = xr[ch1];
        else if (ch1 == 61)  f1 = gx;
        else                 f1 = gz;
        float v0 = t.x * f0;
        float v1 = t.y * f1;
#pragma unroll
        for (int off = 8; off >= 1; off >>= 1) {
            v0 = fmaxf(v0, __shfl_xor_sync(0xffffffffu, v0, off));
            v1 = fmaxf(v1, __shfl_xor_sync(0xffffffffu, v1, off));
        }
        if (k == 0) {
            outp[ch0] = fmaxf(v0, 0.f);
            outp[ch1] = fmaxf(v1, 0.f);
        }
    }
}

// ======== K3: GEMM1 [16384,64]@[64,128] + fb1, fused col-stats ==============
__global__ __launch_bounds__(256) void gemm1_kernel(
    const float* __restrict__ fw1, const float* __restrict__ fb1) {
    extern __shared__ float dyn[];
    float* sW    = dyn;                 // 64*128
    float* sAT   = dyn + 8192;          // 64*36
    float* sred  = dyn + 8192 + 2304;   // 8*128
    float* sqred = sred + 1024;
    const int tid = threadIdx.x;
    const int r0  = blockIdx.x * 32;

    for (int i = tid; i < 2048; i += 256)
        ((float4*)sW)[i] = ((const float4*)fw1)[i];
    for (int i = tid; i < 32*64; i += 256) {
        const int r = i >> 6, c = i & 63;
        sAT[c*36 + r] = g_feat1[(size_t)(r0 + r) * INF + c];
    }
    __syncthreads();

    const int cg = tid & 31;
    const int rg = tid >> 5;
    const float4 fb = reinterpret_cast<const float4*>(fb1)[cg];
    u64 accp[4][2];
#pragma unroll
    for (int i = 0; i < 4; i++) { accp[i][0] = pk(fb.x, fb.y); accp[i][1] = pk(fb.z, fb.w); }

    const ulonglong2* sWq = (const ulonglong2*)sW;
#pragma unroll 4
    for (int kk = 0; kk < 64; kk++) {
        const float4 a = *reinterpret_cast<const float4*>(&sAT[kk*36 + 4*rg]);
        const ulonglong2 ww = sWq[kk*32 + cg];
        const float av[4] = {a.x, a.y, a.z, a.w};
#pragma unroll
        for (int i = 0; i < 4; i++) {
            const u64 aa = pk2(av[i]);
            accp[i][0] = fma2(aa, ww.x, accp[i][0]);
            accp[i][1] = fma2(aa, ww.y, accp[i][1]);
        }
    }
    float s[4] = {0,0,0,0}, sq[4] = {0,0,0,0};
#pragma unroll
    for (int i = 0; i < 4; i++) {
        const float2 lo = upk(accp[i][0]), hi = upk(accp[i][1]);
        float4 o = make_float4(lo.x, lo.y, hi.x, hi.y);
        *reinterpret_cast<float4*>(&g_lin1[(size_t)(r0 + 4*rg + i) * OUTF + 4*cg]) = o;
        s[0] += o.x; s[1] += o.y; s[2] += o.z; s[3] += o.w;
        sq[0] = fmaf(o.x,o.x,sq[0]); sq[1] = fmaf(o.y,o.y,sq[1]);
        sq[2] = fmaf(o.z,o.z,sq[2]); sq[3] = fmaf(o.w,o.w,sq[3]);
    }
#pragma unroll
    for (int qq = 0; qq < 4; qq++) { sred[rg*128 + 4*cg + qq] = s[qq]; sqred[rg*128 + 4*cg + qq] = sq[qq]; }
    __syncthreads();
    if (tid < 128) {
        float a = 0.f, v = 0.f;
#pragma unroll
        for (int r = 0; r < 8; r++) { a += sred[r*128 + tid]; v += sqred[r*128 + tid]; }
        g_part[blockIdx.x*256 + tid]       = a;
        g_part[blockIdx.x*256 + 128 + tid] = v;
    }
}

// ==== K4: GEMM2 with BN1+relu on load, [16384,128]@[128,128]+fb2, stats =====
__global__ __launch_bounds__(256) void gemm2_kernel(
    const float* __restrict__ fw2, const float* __restrict__ fb2) {
    extern __shared__ float dyn[];
    float* sW    = dyn;                  // 128*128
    float* sAT   = dyn + 16384;          // 128*36
    float* sred  = dyn + 16384 + 4608;   // 8*128
    float* sqred = sred + 1024;
    const int tid = threadIdx.x;
    const int r0  = blockIdx.x * 32;

    for (int i = tid; i < 4096; i += 256)
        ((float4*)sW)[i] = ((const float4*)fw2)[i];
    const float* bn = g_bn;       // stage 0
    for (int i = tid; i < 32*128; i += 256) {
        const int r = i >> 7, c = i & 127;
        float v = g_lin1[(size_t)(r0 + r) * OUTF + c];
        v = fmaf(v, bn[c], bn[128 + c]);
        sAT[c*36 + r] = fmaxf(v, 0.f);
    }
    __syncthreads();

    const int cg = tid & 31;
    const int rg = tid >> 5;
    const float4 fb = reinterpret_cast<const float4*>(fb2)[cg];
    u64 accp[4][2];
#pragma unroll
    for (int i = 0; i < 4; i++) { accp[i][0] = pk(fb.x, fb.y); accp[i][1] = pk(fb.z, fb.w); }

    const ulonglong2* sWq = (const ulonglong2*)sW;
#pragma unroll 4
    for (int kk = 0; kk < 128; kk++) {
        const float4 a = *reinterpret_cast<const float4*>(&sAT[kk*36 + 4*rg]);
        const ulonglong2 ww = sWq[kk*32 + cg];
        const float av[4] = {a.x, a.y, a.z, a.w};
#pragma unroll
        for (int i = 0; i < 4; i++) {
            const u64 aa = pk2(av[i]);
            accp[i][0] = fma2(aa, ww.x, accp[i][0]);
            accp[i][1] = fma2(aa, ww.y, accp[i][1]);
        }
    }
    float s[4] = {0,0,0,0}, sq[4] = {0,0,0,0};
#pragma unroll
    for (int i = 0; i < 4; i++) {
        const float2 lo = upk(accp[i][0]), hi = upk(accp[i][1]);
        float4 o = make_float4(lo.x, lo.y, hi.x, hi.y);
        *reinterpret_cast<float4*>(&g_lin2[(size_t)(r0 + 4*rg + i) * OUTF + 4*cg]) = o;
        s[0] += o.x; s[1] += o.y; s[2] += o.z; s[3] += o.w;
        sq[0] = fmaf(o.x,o.x,sq[0]); sq[1] = fmaf(o.y,o.y,sq[1]);
        sq[2] = fmaf(o.z,o.z,sq[2]); sq[3] = fmaf(o.w,o.w,sq[3]);
    }
#pragma unroll
    for (int qq = 0; qq < 4; qq++) { sred[rg*128 + 4*cg + qq] = s[qq]; sqred[rg*128 + 4*cg + qq] = sq[qq]; }
    __syncthreads();
    if (tid < 128) {
        float a = 0.f, v = 0.f;
#pragma unroll
        for (int r = 0; r < 8; r++) { a += sred[r*128 + tid]; v += sqred[r*128 + tid]; }
        g_part[512*256 + blockIdx.x*256 + tid]       = a;
        g_part[512*256 + blockIdx.x*256 + 128 + tid] = v;
    }
}

// ======== finalize BN coefficients (parallelized: 1024 threads) =============
__global__ __launch_bounds__(1024) void finstats_kernel(
    int sel, const float* __restrict__ gamma, const float* __restrict__ beta) {
    __shared__ float red[4*256];
    __shared__ float tot[256];
    const float* part = g_part + sel * (512*256);
    float* bn = g_bn + sel * (2*OUTF);
    const int t = threadIdx.x;
    const int c = t & 255;
    const int g = t >> 8;
    float s = 0.f;
    const int rbeg = g * 128;
#pragma unroll 4
    for (int i = 0; i < 128; i++) s += part[(rbeg + i)*256 + c];
    red[g*256 + c] = s;
    __syncthreads();
    if (t < 256) tot[t] = (red[t] + red[256 + t]) + (red[512 + t] + red[768 + t]);
    __syncthreads();
    if (t < 128) {
        const float inv_n = 1.f / (float)NROW;
        const float m  = tot[t] * inv_n;
        const float v  = tot[128 + t] * inv_n - m * m;
        const float rs = rsqrtf(v + 1e-5f);
        const float a  = rs * gamma[t];
        bn[t]       = a;
        bn[128 + t] = beta[t] - m * a;
    }
}

// ===================== K7: final BN2 -> output (vectorized) =================
__global__ __launch_bounds__(1024) void final_kernel(float* __restrict__ out) {
    const int i = blockIdx.x * 1024 + threadIdx.x;   // float4 units
    const int c0 = (i << 2) & 127;
    const float* bn = g_bn + 2*OUTF;
    const float4 v = ((const float4*)g_lin2)[i];
    float4 o;
    o.x = fmaf(v.x, bn[c0],   bn[128 + c0]);
    o.y = fmaf(v.y, bn[c0+1], bn[128 + c0 + 1]);
    o.z = fmaf(v.z, bn[c0+2], bn[128 + c0 + 2]);
    o.w = fmaf(v.w, bn[c0+3], bn[128 + c0 + 3]);
    ((float4*)out)[i] = o;
}

// ============================================================================
extern "C" void kernel_launch(void* const* d_in, const int* in_sizes, int n_in,
                              void* d_out, int out_size) {
    (void)in_sizes; (void)n_in; (void)out_size;
    const float* x   = (const float*)d_in[0];
    const float* pos = (const float*)d_in[1];
    const float* rw1 = (const float*)d_in[2];
    const float* rb1 = (const float*)d_in[3];
    const float* rw2 = (const float*)d_in[4];
    const float* rb2 = (const float*)d_in[5];
    const float* rw3 = (const float*)d_in[6];
    const float* rb3 = (const float*)d_in[7];
    const float* fw1 = (const float*)d_in[8];
    const float* fb1 = (const float*)d_in[9];
    const float* g1  = (const float*)d_in[10];
    const float* b1  = (const float*)d_in[11];
    const float* fw2 = (const float*)d_in[12];
    const float* fb2 = (const float*)d_in[13];
    const float* g2  = (const float*)d_in[14];
    const float* b2  = (const float*)d_in[15];
    float* out = (float*)d_out;

    // 3 nops so the ncu capture (4th launch) lands on knn_kernel.
    nop_kernel<<<1, 32>>>();
    nop_kernel<<<1, 32>>>();
    nop_kernel<<<1, 32>>>();

    const int smem_knn = (NPTS*3 + 2048 + 8 + 512 + 512 + 16 + 4) * 4;  // ~60.4 KB
    cudaFuncSetAttribute(knn_kernel, cudaFuncAttributeMaxDynamicSharedMemorySize, smem_knn);
    knn_kernel<<<1024, 256, smem_knn>>>(pos);

    relconv_kernel<<<NITEM/128, 128>>>(x, pos, rw1, rb1, rw2, rb2, rw3, rb3);

    const int smem1 = (8192 + 2304 + 2048) * 4;
    cudaFuncSetAttribute(gemm1_kernel, cudaFuncAttributeMaxDynamicSharedMemorySize, smem1);
    gemm1_kernel<<<NROW/32, 256, smem1>>>(fw1, fb1);
    finstats_kernel<<<1, 1024>>>(0, g1, b1);

    const int smem2 = (16384 + 4608 + 2048) * 4;
    cudaFuncSetAttribute(gemm2_kernel, cudaFuncAttributeMaxDynamicSharedMemorySize, smem2);
    gemm2_kernel<<<NROW/32, 256, smem2>>>(fw2, fb2);
    finstats_kernel<<<1, 1024>>>(1, g2, b2);

    final_kernel<<<524288/1024, 1024>>>(out);
}

// round 11
// speedup vs baseline: 1.3180x; 1.0815x over previous
#include <cuda_runtime.h>
#include <math.h>

#define BB   4
#define NPTS 4096
#define KNN  16
#define CIN  61
#define INF  64
#define OUTF 128
#define NROW (BB*NPTS)          // 16384
#define NITEM (NROW*KNN)        // 262144

typedef unsigned long long u64;
typedef unsigned int       u32;

// ------------------- device scratch (no allocations allowed) ----------------
__device__ int   g_idx[NITEM];
__device__ float g_feat1[NROW*INF];
__device__ float g_lin1[NROW*OUTF];
__device__ float g_lin2[NROW*OUTF];
__device__ float g_part[2*512*256];
__device__ float g_bn[2*2*OUTF];

// ---------------- packed fp32x2 helpers (FFMA2 pipe) ------------------------
__device__ __forceinline__ u64 pk2(float a) {
    u64 r; asm("mov.b64 %0,{%1,%1};" : "=l"(r) : "f"(a)); return r;
}
__device__ __forceinline__ u64 pk(float lo, float hi) {
    u64 r; asm("mov.b64 %0,{%1,%2};" : "=l"(r) : "f"(lo), "f"(hi)); return r;
}
__device__ __forceinline__ u64 fma2(u64 a, u64 b, u64 c) {
    u64 d; asm("fma.rn.f32x2 %0,%1,%2,%3;" : "=l"(d) : "l"(a), "l"(b), "l"(c)); return d;
}
__device__ __forceinline__ float2 upk(u64 v) {
    float2 f; asm("mov.b64 {%0,%1},%2;" : "=f"(f.x), "=f"(f.y) : "l"(v)); return f;
}

// ----------------------- profiling alignment nop ----------------------------
__global__ void nop_kernel() {}

// ===== K1: exact KNN v7 — radix histogram, register candidates, full occ ====
// 1024 blocks x 512 threads; block = 16 queries of one batch, sequential.
// 8 candidates per thread in registers (reused across the 16 queries).
__global__ __launch_bounds__(512, 2) void knn_kernel(const float* __restrict__ pos) {
    extern __shared__ float sm[];
    float* sp    = sm;                        // [NPTS*3]
    u32*   hist  = (u32*)(sm + NPTS*3);       // [2048]
    u32*   swarp = hist + 2048;               // [16]
    u32*   listv = swarp + 16;                // [512]
    int*   listj = (int*)(listv + 512);       // [512]
    int*   outj  = listj + 512;               // [16]
    int*   ctl   = outj + 16;                 // [4]

    const int tid  = threadIdx.x;
    const int lane = tid & 31;
    const int wid  = tid >> 5;
    const int b    = blockIdx.x >> 8;         // 256 blocks per batch
    const int q0   = (blockIdx.x & 255) << 4; // 16 queries per block
    const float* pb = pos + (size_t)b * NPTS * 3;

    for (int i = tid; i < NPTS*3; i += 512) sp[i] = pb[i];
    __syncthreads();

    // candidate coords -> registers (fixed across all queries of this block)
    float px[8], py[8], pz[8];
#pragma unroll
    for (int t = 0; t < 8; t++) {
        const int j = tid + 512*t;
        px[t] = sp[3*j]; py[t] = sp[3*j+1]; pz[t] = sp[3*j+2];
    }

    for (int qi = 0; qi < 16; qi++) {
        const int q = q0 + qi;
        // clear histogram: one uint4 store per thread + counters
        ((uint4*)hist)[tid] = make_uint4(0,0,0,0);
        if (tid == 0) { ctl[0] = 0; ctl[1] = 0; }
        __syncthreads();

        const float qx = sp[3*q], qy = sp[3*q+1], qz = sp[3*q+2];

        // distance keys in registers + histogram build
        u32 kk[8];
#pragma unroll
        for (int t = 0; t < 8; t++) {
            const float dx = qx - px[t], dy = qy - py[t], dz = qz - pz[t];
            // match XLA rounding: no fma contraction, left-to-right sum
            kk[t] = __float_as_uint(__fadd_rn(__fadd_rn(__fmul_rn(dx,dx),
                        __fmul_rn(dy,dy)), __fmul_rn(dz,dz)));
            atomicAdd(&hist[kk[t] >> 21], 1u);
        }
        __syncthreads();

        // prefix over 512 chunks of 4 bins: warp shfl scan + cross-warp fixup
        u32 part;
        {
            const uint4 h4 = ((const uint4*)hist)[tid];
            part = (h4.x + h4.y) + (h4.z + h4.w);
        }
        u32 v = part;
#pragma unroll
        for (int off = 1; off < 32; off <<= 1) {
            u32 nb = __shfl_up_sync(0xffffffffu, v, off);
            if (lane >= off) v += nb;
        }
        if (lane == 31) swarp[wid] = v;
        __syncthreads();
        u32 base = 0;
#pragma unroll
        for (int w = 0; w < 16; w++) base += (w < wid) ? swarp[w] : 0u;
        const u32 incl = base + v, excl = incl - part;
        if (excl < 16u && incl >= 16u) {
            u32 c = excl;
#pragma unroll
            for (int k2 = 0; k2 < 4; k2++) {
                const u32 h = hist[tid*4 + k2];
                if (c < 16u && c + h >= 16u) { ctl[2] = tid*4 + k2; ctl[3] = (int)c; break; }
                c += h;
            }
        }
        __syncthreads();
        const u32 bstar = (u32)ctl[2];
        const int Lb    = ctl[3];

        // classify from register keys: below-bin -> top-16 (set order free);
        // boundary-bin -> candidate list
#pragma unroll
        for (int t = 0; t < 8; t++) {
            const u32 key = kk[t] >> 21;
            if (key < bstar) {
                const int p = atomicAdd(&ctl[0], 1);
                outj[p] = tid + 512*t;
            } else if (key == bstar) {
                const int p = atomicAdd(&ctl[1], 1);
                if (p < 512) { listv[p] = kk[t]; listj[p] = tid + 512*t; }
            }
        }
        __syncthreads();

        // exact (d2, index) lexicographic rank select inside boundary bin
        const int cnt = min(ctl[1], 512), need = 16 - Lb;
        if (tid < cnt) {
            const u64 me = ((u64)listv[tid] << 32) | (u32)listj[tid];
            int rank = 0;
            for (int i = 0; i < cnt; i++)
                rank += ((((u64)listv[i] << 32) | (u32)listj[i]) < me);
            if (rank < need) outj[Lb + rank] = listj[tid];
        }
        __syncthreads();
        if (tid < 16) g_idx[((b*NPTS + q) << 4) + tid] = outj[tid];
        __syncthreads();
    }
}

// ============ K2: per-neighbor MLP + weighted max-pool (FFMA2) ==============
__global__ __launch_bounds__(128) void relconv_kernel(
    const float* __restrict__ x, const float* __restrict__ pos,
    const float* __restrict__ rw1, const float* __restrict__ rb1,
    const float* __restrict__ rw2, const float* __restrict__ rb2,
    const float* __restrict__ rw3, const float* __restrict__ rb3) {

    __shared__ __align__(16) float sw1[10*32];
    __shared__ __align__(16) float sb1[32];
    __shared__ __align__(16) float sw2[32*64];
    __shared__ __align__(16) float sb2[64];
    __shared__ __align__(16) float sw3[64*64];
    __shared__ __align__(16) float sb3[64];

    const int tid = threadIdx.x;
    for (int i = tid; i < 320;  i += 128) sw1[i] = rw1[i];
    for (int i = tid; i < 32;   i += 128) sb1[i] = rb1[i];
    for (int i = tid; i < 2048; i += 128) sw2[i] = rw2[i];
    for (int i = tid; i < 64;   i += 128) sb2[i] = rb2[i];
    for (int i = tid; i < 4096; i += 128) sw3[i] = rw3[i];
    for (int i = tid; i < 64;   i += 128) sb3[i] = rb3[i];
    __syncthreads();

    const int item = blockIdx.x * 128 + tid;
    const int k = item & (KNN-1);
    const int n = (item >> 4) & (NPTS-1);
    const int b = item >> 16;
    const int j = g_idx[item];

    const float* pb = pos + (size_t)b * NPTS * 3;
    const float cx = pb[3*n], cy = pb[3*n+1], cz = pb[3*n+2];
    const float gx = pb[3*j], gy = pb[3*j+1], gz = pb[3*j+2];
    const float rx = gx - cx, ry = gy - cy, rz = gz - cz;
    const float s2 = rx*rx + ry*ry + rz*rz;
    const float dis = (s2 > 0.f) ? sqrtf(s2) : 0.f;

    const float f[10] = {cx, cy, cz, gx, gy, gz, rx, ry, rz, dis};

    const ulonglong2* w1q = (const ulonglong2*)sw1;
    const ulonglong2* w2q = (const ulonglong2*)sw2;
    const ulonglong2* w3q = (const ulonglong2*)sw3;

    // layer1: 10 -> 32, relu
    u64 h1p[16];
#pragma unroll
    for (int d = 0; d < 16; d++) h1p[d] = ((const u64*)sb1)[d];
#pragma unroll
    for (int c = 0; c < 10; c++) {
        const u64 aa = pk2(f[c]);
#pragma unroll
        for (int dq = 0; dq < 8; dq++) {
            const ulonglong2 ww = w1q[c*8 + dq];
            h1p[2*dq]   = fma2(aa, ww.x, h1p[2*dq]);
            h1p[2*dq+1] = fma2(aa, ww.y, h1p[2*dq+1]);
        }
    }
    float h1[32];
#pragma unroll
    for (int d = 0; d < 16; d++) {
        float2 t = upk(h1p[d]);
        h1[2*d]   = fmaxf(t.x, 0.f);
        h1[2*d+1] = fmaxf(t.y, 0.f);
    }

    // layer2: 32 -> 64, relu
    u64 h2p[32];
#pragma unroll
    for (int d = 0; d < 32; d++) h2p[d] = ((const u64*)sb2)[d];
#pragma unroll
    for (int c = 0; c < 32; c++) {
        const u64 aa = pk2(h1[c]);
#pragma unroll
        for (int dq = 0; dq < 16; dq++) {
            const ulonglong2 ww = w2q[c*16 + dq];
            h2p[2*dq]   = fma2(aa, ww.x, h2p[2*dq]);
            h2p[2*dq+1] = fma2(aa, ww.y, h2p[2*dq+1]);
        }
    }
    float h2[64];
#pragma unroll
    for (int d = 0; d < 32; d++) {
        float2 t = upk(h2p[d]);
        h2[2*d]   = fmaxf(t.x, 0.f);
        h2[2*d+1] = fmaxf(t.y, 0.f);
    }

    // layer3: 64 -> 64, no relu
    u64 wp[32];
#pragma unroll
    for (int d = 0; d < 32; d++) wp[d] = ((const u64*)sb3)[d];
#pragma unroll
    for (int c = 0; c < 64; c++) {
        const u64 aa = pk2(h2[c]);
#pragma unroll
        for (int dq = 0; dq < 16; dq++) {
            const ulonglong2 ww = w3q[c*16 + dq];
            wp[2*dq]   = fma2(aa, ww.x, wp[2*dq]);
            wp[2*dq+1] = fma2(aa, ww.y, wp[2*dq+1]);
        }
    }

    // weights * feat, warp max over k (16 lanes), relu, store (k==0 lane)
    const float* xr = x + ((size_t)b * NPTS + j) * CIN;
    float* outp = g_feat1 + ((size_t)b * NPTS + n) * INF;
#pragma unroll
    for (int d = 0; d < 32; d++) {
        const float2 t = upk(wp[d]);
        const int ch0 = 2*d, ch1 = 2*d + 1;
        float f0, f1;
        if (ch0 < CIN)       f0 = xr[ch0];
        else if (ch0 == 62)  f0 = gy;
        else                 f0 = gx;
        if (ch1 < CIN)       f1 = xr[ch1];
        else if (ch1 == 61)  f1 = gx;
        else                 f1 = gz;
        float v0 = t.x * f0;
        float v1 = t.y * f1;
#pragma unroll
        for (int off = 8; off >= 1; off >>= 1) {
            v0 = fmaxf(v0, __shfl_xor_sync(0xffffffffu, v0, off));
            v1 = fmaxf(v1, __shfl_xor_sync(0xffffffffu, v1, off));
        }
        if (k == 0) {
            outp[ch0] = fmaxf(v0, 0.f);
            outp[ch1] = fmaxf(v1, 0.f);
        }
    }
}

// ======== K3: GEMM1 [16384,64]@[64,128] + fb1, fused col-stats ==============
__global__ __launch_bounds__(256) void gemm1_kernel(
    const float* __restrict__ fw1, const float* __restrict__ fb1) {
    extern __shared__ float dyn[];
    float* sW    = dyn;                 // 64*128
    float* sAT   = dyn + 8192;          // 64*36
    float* sred  = dyn + 8192 + 2304;   // 8*128
    float* sqred = sred + 1024;
    const int tid = threadIdx.x;
    const int r0  = blockIdx.x * 32;

    for (int i = tid; i < 2048; i += 256)
        ((float4*)sW)[i] = ((const float4*)fw1)[i];
    for (int i = tid; i < 32*64; i += 256) {
        const int r = i >> 6, c = i & 63;
        sAT[c*36 + r] = g_feat1[(size_t)(r0 + r) * INF + c];
    }
    __syncthreads();

    const int cg = tid & 31;
    const int rg = tid >> 5;
    const float4 fb = reinterpret_cast<const float4*>(fb1)[cg];
    u64 accp[4][2];
#pragma unroll
    for (int i = 0; i < 4; i++) { accp[i][0] = pk(fb.x, fb.y); accp[i][1] = pk(fb.z, fb.w); }

    const ulonglong2* sWq = (const ulonglong2*)sW;
#pragma unroll 4
    for (int kk = 0; kk < 64; kk++) {
        const float4 a = *reinterpret_cast<const float4*>(&sAT[kk*36 + 4*rg]);
        const ulonglong2 ww = sWq[kk*32 + cg];
        const float av[4] = {a.x, a.y, a.z, a.w};
#pragma unroll
        for (int i = 0; i < 4; i++) {
            const u64 aa = pk2(av[i]);
            accp[i][0] = fma2(aa, ww.x, accp[i][0]);
            accp[i][1] = fma2(aa, ww.y, accp[i][1]);
        }
    }
    float s[4] = {0,0,0,0}, sq[4] = {0,0,0,0};
#pragma unroll
    for (int i = 0; i < 4; i++) {
        const float2 lo = upk(accp[i][0]), hi = upk(accp[i][1]);
        float4 o = make_float4(lo.x, lo.y, hi.x, hi.y);
        *reinterpret_cast<float4*>(&g_lin1[(size_t)(r0 + 4*rg + i) * OUTF + 4*cg]) = o;
        s[0] += o.x; s[1] += o.y; s[2] += o.z; s[3] += o.w;
        sq[0] = fmaf(o.x,o.x,sq[0]); sq[1] = fmaf(o.y,o.y,sq[1]);
        sq[2] = fmaf(o.z,o.z,sq[2]); sq[3] = fmaf(o.w,o.w,sq[3]);
    }
#pragma unroll
    for (int qq = 0; qq < 4; qq++) { sred[rg*128 + 4*cg + qq] = s[qq]; sqred[rg*128 + 4*cg + qq] = sq[qq]; }
    __syncthreads();
    if (tid < 128) {
        float a = 0.f, v = 0.f;
#pragma unroll
        for (int r = 0; r < 8; r++) { a += sred[r*128 + tid]; v += sqred[r*128 + tid]; }
        g_part[blockIdx.x*256 + tid]       = a;
        g_part[blockIdx.x*256 + 128 + tid] = v;
    }
}

// ==== K4: GEMM2 with BN1+relu on load, [16384,128]@[128,128]+fb2, stats =====
__global__ __launch_bounds__(256) void gemm2_kernel(
    const float* __restrict__ fw2, const float* __restrict__ fb2) {
    extern __shared__ float dyn[];
    float* sW    = dyn;                  // 128*128
    float* sAT   = dyn + 16384;          // 128*36
    float* sred  = dyn + 16384 + 4608;   // 8*128
    float* sqred = sred + 1024;
    const int tid = threadIdx.x;
    const int r0  = blockIdx.x * 32;

    for (int i = tid; i < 4096; i += 256)
        ((float4*)sW)[i] = ((const float4*)fw2)[i];
    const float* bn = g_bn;       // stage 0
    for (int i = tid; i < 32*128; i += 256) {
        const int r = i >> 7, c = i & 127;
        float v = g_lin1[(size_t)(r0 + r) * OUTF + c];
        v = fmaf(v, bn[c], bn[128 + c]);
        sAT[c*36 + r] = fmaxf(v, 0.f);
    }
    __syncthreads();

    const int cg = tid & 31;
    const int rg = tid >> 5;
    const float4 fb = reinterpret_cast<const float4*>(fb2)[cg];
    u64 accp[4][2];
#pragma unroll
    for (int i = 0; i < 4; i++) { accp[i][0] = pk(fb.x, fb.y); accp[i][1] = pk(fb.z, fb.w); }

    const ulonglong2* sWq = (const ulonglong2*)sW;
#pragma unroll 4
    for (int kk = 0; kk < 128; kk++) {
        const float4 a = *reinterpret_cast<const float4*>(&sAT[kk*36 + 4*rg]);
        const ulonglong2 ww = sWq[kk*32 + cg];
        const float av[4] = {a.x, a.y, a.z, a.w};
#pragma unroll
        for (int i = 0; i < 4; i++) {
            const u64 aa = pk2(av[i]);
            accp[i][0] = fma2(aa, ww.x, accp[i][0]);
            accp[i][1] = fma2(aa, ww.y, accp[i][1]);
        }
    }
    float s[4] = {0,0,0,0}, sq[4] = {0,0,0,0};
#pragma unroll
    for (int i = 0; i < 4; i++) {
        const float2 lo = upk(accp[i][0]), hi = upk(accp[i][1]);
        float4 o = make_float4(lo.x, lo.y, hi.x, hi.y);
        *reinterpret_cast<float4*>(&g_lin2[(size_t)(r0 + 4*rg + i) * OUTF + 4*cg]) = o;
        s[0] += o.x; s[1] += o.y; s[2] += o.z; s[3] += o.w;
        sq[0] = fmaf(o.x,o.x,sq[0]); sq[1] = fmaf(o.y,o.y,sq[1]);
        sq[2] = fmaf(o.z,o.z,sq[2]); sq[3] = fmaf(o.w,o.w,sq[3]);
    }
#pragma unroll
    for (int qq = 0; qq < 4; qq++) { sred[rg*128 + 4*cg + qq] = s[qq]; sqred[rg*128 + 4*cg + qq] = sq[qq]; }
    __syncthreads();
    if (tid < 128) {
        float a = 0.f, v = 0.f;
#pragma unroll
        for (int r = 0; r < 8; r++) { a += sred[r*128 + tid]; v += sqred[r*128 + tid]; }
        g_part[512*256 + blockIdx.x*256 + tid]       = a;
        g_part[512*256 + blockIdx.x*256 + 128 + tid] = v;
    }
}

// ======== finalize BN coefficients (parallelized: 1024 threads) =============
__global__ __launch_bounds__(1024) void finstats_kernel(
    int sel, const float* __restrict__ gamma, const float* __restrict__ beta) {
    __shared__ float red[4*256];
    __shared__ float tot[256];
    const float* part = g_part + sel * (512*256);
    float* bn = g_bn + sel * (2*OUTF);
    const int t = threadIdx.x;
    const int c = t & 255;
    const int g = t >> 8;
    float s = 0.f;
    const int rbeg = g * 128;
#pragma unroll 4
    for (int i = 0; i < 128; i++) s += part[(rbeg + i)*256 + c];
    red[g*256 + c] = s;
    __syncthreads();
    if (t < 256) tot[t] = (red[t] + red[256 + t]) + (red[512 + t] + red[768 + t]);
    __syncthreads();
    if (t < 128) {
        const float inv_n = 1.f / (float)NROW;
        const float m  = tot[t] * inv_n;
        const float v  = tot[128 + t] * inv_n - m * m;
        const float rs = rsqrtf(v + 1e-5f);
        const float a  = rs * gamma[t];
        bn[t]       = a;
        bn[128 + t] = beta[t] - m * a;
    }
}

// ===================== K7: final BN2 -> output (vectorized) =================
__global__ __launch_bounds__(1024) void final_kernel(float* __restrict__ out) {
    const int i = blockIdx.x * 1024 + threadIdx.x;   // float4 units
    const int c0 = (i << 2) & 127;
    const float* bn = g_bn + 2*OUTF;
    const float4 v = ((const float4*)g_lin2)[i];
    float4 o;
    o.x = fmaf(v.x, bn[c0],   bn[128 + c0]);
    o.y = fmaf(v.y, bn[c0+1], bn[128 + c0 + 1]);
    o.z = fmaf(v.z, bn[c0+2], bn[128 + c0 + 2]);
    o.w = fmaf(v.w, bn[c0+3], bn[128 + c0 + 3]);
    ((float4*)out)[i] = o;
}

// ============================================================================
extern "C" void kernel_launch(void* const* d_in, const int* in_sizes, int n_in,
                              void* d_out, int out_size) {
    (void)in_sizes; (void)n_in; (void)out_size;
    const float* x   = (const float*)d_in[0];
    const float* pos = (const float*)d_in[1];
    const float* rw1 = (const float*)d_in[2];
    const float* rb1 = (const float*)d_in[3];
    const float* rw2 = (const float*)d_in[4];
    const float* rb2 = (const float*)d_in[5];
    const float* rw3 = (const float*)d_in[6];
    const float* rb3 = (const float*)d_in[7];
    const float* fw1 = (const float*)d_in[8];
    const float* fb1 = (const float*)d_in[9];
    const float* g1  = (const float*)d_in[10];
    const float* b1  = (const float*)d_in[11];
    const float* fw2 = (const float*)d_in[12];
    const float* fb2 = (const float*)d_in[13];
    const float* g2  = (const float*)d_in[14];
    const float* b2  = (const float*)d_in[15];
    float* out = (float*)d_out;

    // 2 nops so the ncu capture (4th launch) lands on relconv_kernel.
    nop_kernel<<<1, 32>>>();
    nop_kernel<<<1, 32>>>();

    const int smem_knn = (NPTS*3 + 2048 + 16 + 512 + 512 + 16 + 4) * 4;  // ~60.4 KB
    cudaFuncSetAttribute(knn_kernel, cudaFuncAttributeMaxDynamicSharedMemorySize, smem_knn);
    knn_kernel<<<1024, 512, smem_knn>>>(pos);

    relconv_kernel<<<NITEM/128, 128>>>(x, pos, rw1, rb1, rw2, rb2, rw3, rb3);

    const int smem1 = (8192 + 2304 + 2048) * 4;
    cudaFuncSetAttribute(gemm1_kernel, cudaFuncAttributeMaxDynamicSharedMemorySize, smem1);
    gemm1_kernel<<<NROW/32, 256, smem1>>>(fw1, fb1);
    finstats_kernel<<<1, 1024>>>(0, g1, b1);

    const int smem2 = (16384 + 4608 + 2048) * 4;
    cudaFuncSetAttribute(gemm2_kernel, cudaFuncAttributeMaxDynamicSharedMemorySize, smem2);
    gemm2_kernel<<<NROW/32, 256, smem2>>>(fw2, fb2);
    finstats_kernel<<<1, 1024>>>(1, g2, b2);

    final_kernel<<<524288/1024, 1024>>>(out);
}

// round 12
// speedup vs baseline: 1.4764x; 1.1202x over previous
#include <cuda_runtime.h>
#include <math.h>

#define BB   4
#define NPTS 4096
#define KNN  16
#define CIN  61
#define INF  64
#define OUTF 128
#define NROW (BB*NPTS)          // 16384
#define NITEM (NROW*KNN)        // 262144

typedef unsigned long long u64;
typedef unsigned int       u32;

// ------------------- device scratch (no allocations allowed) ----------------
__device__ int   g_idx[NITEM];
__device__ float g_feat1[NROW*INF];
__device__ float g_lin1[NROW*OUTF];
__device__ float g_lin2[NROW*OUTF];
__device__ float g_part[2*512*256];
__device__ float g_bn[2*2*OUTF];

// ---------- MLP weights in constant memory (separate cache port) ------------
__constant__ __align__(16) float cw1[10*32];
__constant__ __align__(16) float cb1[32];
__constant__ __align__(16) float cw2[32*64];
__constant__ __align__(16) float cb2[64];
__constant__ __align__(16) float cw3[64*64];
__constant__ __align__(16) float cb3[64];

// ---------------- packed fp32x2 helpers (FFMA2 pipe) ------------------------
__device__ __forceinline__ u64 pk2(float a) {
    u64 r; asm("mov.b64 %0,{%1,%1};" : "=l"(r) : "f"(a)); return r;
}
__device__ __forceinline__ u64 pk(float lo, float hi) {
    u64 r; asm("mov.b64 %0,{%1,%2};" : "=l"(r) : "f"(lo), "f"(hi)); return r;
}
__device__ __forceinline__ u64 fma2(u64 a, u64 b, u64 c) {
    u64 d; asm("fma.rn.f32x2 %0,%1,%2,%3;" : "=l"(d) : "l"(a), "l"(b), "l"(c)); return d;
}
__device__ __forceinline__ float2 upk(u64 v) {
    float2 f; asm("mov.b64 {%0,%1},%2;" : "=f"(f.x), "=f"(f.y) : "l"(v)); return f;
}

// ----------------------- profiling alignment nop ----------------------------
__global__ void nop_kernel() {}

// ===== K1: exact KNN v7 — radix histogram, register candidates, full occ ====
__global__ __launch_bounds__(512, 2) void knn_kernel(const float* __restrict__ pos) {
    extern __shared__ float sm[];
    float* sp    = sm;                        // [NPTS*3]
    u32*   hist  = (u32*)(sm + NPTS*3);       // [2048]
    u32*   swarp = hist + 2048;               // [16]
    u32*   listv = swarp + 16;                // [512]
    int*   listj = (int*)(listv + 512);       // [512]
    int*   outj  = listj + 512;               // [16]
    int*   ctl   = outj + 16;                 // [4]

    const int tid  = threadIdx.x;
    const int lane = tid & 31;
    const int wid  = tid >> 5;
    const int b    = blockIdx.x >> 8;
    const int q0   = (blockIdx.x & 255) << 4;
    const float* pb = pos + (size_t)b * NPTS * 3;

    for (int i = tid; i < NPTS*3; i += 512) sp[i] = pb[i];
    __syncthreads();

    float px[8], py[8], pz[8];
#pragma unroll
    for (int t = 0; t < 8; t++) {
        const int j = tid + 512*t;
        px[t] = sp[3*j]; py[t] = sp[3*j+1]; pz[t] = sp[3*j+2];
    }

    for (int qi = 0; qi < 16; qi++) {
        const int q = q0 + qi;
        ((uint4*)hist)[tid] = make_uint4(0,0,0,0);
        if (tid == 0) { ctl[0] = 0; ctl[1] = 0; }
        __syncthreads();

        const float qx = sp[3*q], qy = sp[3*q+1], qz = sp[3*q+2];

        u32 kk[8];
#pragma unroll
        for (int t = 0; t < 8; t++) {
            const float dx = qx - px[t], dy = qy - py[t], dz = qz - pz[t];
            // match XLA rounding: no fma contraction, left-to-right sum
            kk[t] = __float_as_uint(__fadd_rn(__fadd_rn(__fmul_rn(dx,dx),
                        __fmul_rn(dy,dy)), __fmul_rn(dz,dz)));
            atomicAdd(&hist[kk[t] >> 21], 1u);
        }
        __syncthreads();

        u32 part;
        {
            const uint4 h4 = ((const uint4*)hist)[tid];
            part = (h4.x + h4.y) + (h4.z + h4.w);
        }
        u32 v = part;
#pragma unroll
        for (int off = 1; off < 32; off <<= 1) {
            u32 nb = __shfl_up_sync(0xffffffffu, v, off);
            if (lane >= off) v += nb;
        }
        if (lane == 31) swarp[wid] = v;
        __syncthreads();
        u32 base = 0;
#pragma unroll
        for (int w = 0; w < 16; w++) base += (w < wid) ? swarp[w] : 0u;
        const u32 incl = base + v, excl = incl - part;
        if (excl < 16u && incl >= 16u) {
            u32 c = excl;
#pragma unroll
            for (int k2 = 0; k2 < 4; k2++) {
                const u32 h = hist[tid*4 + k2];
                if (c < 16u && c + h >= 16u) { ctl[2] = tid*4 + k2; ctl[3] = (int)c; break; }
                c += h;
            }
        }
        __syncthreads();
        const u32 bstar = (u32)ctl[2];
        const int Lb    = ctl[3];

#pragma unroll
        for (int t = 0; t < 8; t++) {
            const u32 key = kk[t] >> 21;
            if (key < bstar) {
                const int p = atomicAdd(&ctl[0], 1);
                outj[p] = tid + 512*t;
            } else if (key == bstar) {
                const int p = atomicAdd(&ctl[1], 1);
                if (p < 512) { listv[p] = kk[t]; listj[p] = tid + 512*t; }
            }
        }
        __syncthreads();

        const int cnt = min(ctl[1], 512), need = 16 - Lb;
        if (tid < cnt) {
            const u64 me = ((u64)listv[tid] << 32) | (u32)listj[tid];
            int rank = 0;
            for (int i = 0; i < cnt; i++)
                rank += ((((u64)listv[i] << 32) | (u32)listj[i]) < me);
            if (rank < need) outj[Lb + rank] = listj[tid];
        }
        __syncthreads();
        if (tid < 16) g_idx[((b*NPTS + q) << 4) + tid] = outj[tid];
        __syncthreads();
    }
}

// ====== K2: per-neighbor MLP (weights in __constant__) + max-pool ===========
__global__ __launch_bounds__(128) void relconv_kernel(
    const float* __restrict__ x, const float* __restrict__ pos) {

    const int tid = threadIdx.x;
    const int item = blockIdx.x * 128 + tid;
    const int k = item & (KNN-1);
    const int n = (item >> 4) & (NPTS-1);
    const int b = item >> 16;
    const int j = g_idx[item];

    const float* pb = pos + (size_t)b * NPTS * 3;
    const float cx = pb[3*n], cy = pb[3*n+1], cz = pb[3*n+2];
    const float gx = pb[3*j], gy = pb[3*j+1], gz = pb[3*j+2];
    const float rx = gx - cx, ry = gy - cy, rz = gz - cz;
    const float s2 = rx*rx + ry*ry + rz*rz;
    const float dis = (s2 > 0.f) ? sqrtf(s2) : 0.f;

    const float f[10] = {cx, cy, cz, gx, gy, gz, rx, ry, rz, dis};

    // layer1: 10 -> 32, relu  (weights via constant port)
    u64 h1p[16];
#pragma unroll
    for (int d = 0; d < 16; d++) h1p[d] = ((const u64*)cb1)[d];
#pragma unroll
    for (int c = 0; c < 10; c++) {
        const u64 aa = pk2(f[c]);
        const ulonglong2* wrow = (const ulonglong2*)(cw1 + c*32);
#pragma unroll
        for (int dq = 0; dq < 8; dq++) {
            const ulonglong2 ww = wrow[dq];
            h1p[2*dq]   = fma2(aa, ww.x, h1p[2*dq]);
            h1p[2*dq+1] = fma2(aa, ww.y, h1p[2*dq+1]);
        }
    }
    float h1[32];
#pragma unroll
    for (int d = 0; d < 16; d++) {
        float2 t = upk(h1p[d]);
        h1[2*d]   = fmaxf(t.x, 0.f);
        h1[2*d+1] = fmaxf(t.y, 0.f);
    }

    // layer2: 32 -> 64, relu
    u64 h2p[32];
#pragma unroll
    for (int d = 0; d < 32; d++) h2p[d] = ((const u64*)cb2)[d];
#pragma unroll
    for (int c = 0; c < 32; c++) {
        const u64 aa = pk2(h1[c]);
        const ulonglong2* wrow = (const ulonglong2*)(cw2 + c*64);
#pragma unroll
        for (int dq = 0; dq < 16; dq++) {
            const ulonglong2 ww = wrow[dq];
            h2p[2*dq]   = fma2(aa, ww.x, h2p[2*dq]);
            h2p[2*dq+1] = fma2(aa, ww.y, h2p[2*dq+1]);
        }
    }
    float h2[64];
#pragma unroll
    for (int d = 0; d < 32; d++) {
        float2 t = upk(h2p[d]);
        h2[2*d]   = fmaxf(t.x, 0.f);
        h2[2*d+1] = fmaxf(t.y, 0.f);
    }

    // layer3: 64 -> 64, no relu
    u64 wp[32];
#pragma unroll
    for (int d = 0; d < 32; d++) wp[d] = ((const u64*)cb3)[d];
#pragma unroll
    for (int c = 0; c < 64; c++) {
        const u64 aa = pk2(h2[c]);
        const ulonglong2* wrow = (const ulonglong2*)(cw3 + c*64);
#pragma unroll
        for (int dq = 0; dq < 16; dq++) {
            const ulonglong2 ww = wrow[dq];
            wp[2*dq]   = fma2(aa, ww.x, wp[2*dq]);
            wp[2*dq+1] = fma2(aa, ww.y, wp[2*dq+1]);
        }
    }

    // weights * feat, warp max over k (16 lanes), relu, store (k==0 lane)
    const float* xr = x + ((size_t)b * NPTS + j) * CIN;
    float* outp = g_feat1 + ((size_t)b * NPTS + n) * INF;
#pragma unroll
    for (int d = 0; d < 32; d++) {
        const float2 t = upk(wp[d]);
        const int ch0 = 2*d, ch1 = 2*d + 1;
        float f0, f1;
        if (ch0 < CIN)       f0 = xr[ch0];
        else if (ch0 == 62)  f0 = gy;
        else                 f0 = gx;
        if (ch1 < CIN)       f1 = xr[ch1];
        else if (ch1 == 61)  f1 = gx;
        else                 f1 = gz;
        float v0 = t.x * f0;
        float v1 = t.y * f1;
#pragma unroll
        for (int off = 8; off >= 1; off >>= 1) {
            v0 = fmaxf(v0, __shfl_xor_sync(0xffffffffu, v0, off));
            v1 = fmaxf(v1, __shfl_xor_sync(0xffffffffu, v1, off));
        }
        if (k == 0) {
            outp[ch0] = fmaxf(v0, 0.f);
            outp[ch1] = fmaxf(v1, 0.f);
        }
    }
}

// ======== K3: GEMM1 [16384,64]@[64,128] + fb1, fused col-stats ==============
__global__ __launch_bounds__(256) void gemm1_kernel(
    const float* __restrict__ fw1, const float* __restrict__ fb1) {
    extern __shared__ float dyn[];
    float* sW    = dyn;                 // 64*128
    float* sAT   = dyn + 8192;          // 64*36
    float* sred  = dyn + 8192 + 2304;   // 8*128
    float* sqred = sred + 1024;
    const int tid = threadIdx.x;
    const int r0  = blockIdx.x * 32;

    for (int i = tid; i < 2048; i += 256)
        ((float4*)sW)[i] = ((const float4*)fw1)[i];
    for (int i = tid; i < 32*64; i += 256) {
        const int r = i >> 6, c = i & 63;
        sAT[c*36 + r] = g_feat1[(size_t)(r0 + r) * INF + c];
    }
    __syncthreads();

    const int cg = tid & 31;
    const int rg = tid >> 5;
    const float4 fb = reinterpret_cast<const float4*>(fb1)[cg];
    u64 accp[4][2];
#pragma unroll
    for (int i = 0; i < 4; i++) { accp[i][0] = pk(fb.x, fb.y); accp[i][1] = pk(fb.z, fb.w); }

    const ulonglong2* sWq = (const ulonglong2*)sW;
#pragma unroll 4
    for (int kk = 0; kk < 64; kk++) {
        const float4 a = *reinterpret_cast<const float4*>(&sAT[kk*36 + 4*rg]);
        const ulonglong2 ww = sWq[kk*32 + cg];
        const float av[4] = {a.x, a.y, a.z, a.w};
#pragma unroll
        for (int i = 0; i < 4; i++) {
            const u64 aa = pk2(av[i]);
            accp[i][0] = fma2(aa, ww.x, accp[i][0]);
            accp[i][1] = fma2(aa, ww.y, accp[i][1]);
        }
    }
    float s[4] = {0,0,0,0}, sq[4] = {0,0,0,0};
#pragma unroll
    for (int i = 0; i < 4; i++) {
        const float2 lo = upk(accp[i][0]), hi = upk(accp[i][1]);
        float4 o = make_float4(lo.x, lo.y, hi.x, hi.y);
        *reinterpret_cast<float4*>(&g_lin1[(size_t)(r0 + 4*rg + i) * OUTF + 4*cg]) = o;
        s[0] += o.x; s[1] += o.y; s[2] += o.z; s[3] += o.w;
        sq[0] = fmaf(o.x,o.x,sq[0]); sq[1] = fmaf(o.y,o.y,sq[1]);
        sq[2] = fmaf(o.z,o.z,sq[2]); sq[3] = fmaf(o.w,o.w,sq[3]);
    }
#pragma unroll
    for (int qq = 0; qq < 4; qq++) { sred[rg*128 + 4*cg + qq] = s[qq]; sqred[rg*128 + 4*cg + qq] = sq[qq]; }
    __syncthreads();
    if (tid < 128) {
        float a = 0.f, v = 0.f;
#pragma unroll
        for (int r = 0; r < 8; r++) { a += sred[r*128 + tid]; v += sqred[r*128 + tid]; }
        g_part[blockIdx.x*256 + tid]       = a;
        g_part[blockIdx.x*256 + 128 + tid] = v;
    }
}

// ==== K4: GEMM2 with BN1+relu on load, [16384,128]@[128,128]+fb2, stats =====
__global__ __launch_bounds__(256) void gemm2_kernel(
    const float* __restrict__ fw2, const float* __restrict__ fb2) {
    extern __shared__ float dyn[];
    float* sW    = dyn;                  // 128*128
    float* sAT   = dyn + 16384;          // 128*36
    float* sred  = dyn + 16384 + 4608;   // 8*128
    float* sqred = sred + 1024;
    const int tid = threadIdx.x;
    const int r0  = blockIdx.x * 32;

    for (int i = tid; i < 4096; i += 256)
        ((float4*)sW)[i] = ((const float4*)fw2)[i];
    const float* bn = g_bn;       // stage 0
    for (int i = tid; i < 32*128; i += 256) {
        const int r = i >> 7, c = i & 127;
        float v = g_lin1[(size_t)(r0 + r) * OUTF + c];
        v = fmaf(v, bn[c], bn[128 + c]);
        sAT[c*36 + r] = fmaxf(v, 0.f);
    }
    __syncthreads();

    const int cg = tid & 31;
    const int rg = tid >> 5;
    const float4 fb = reinterpret_cast<const float4*>(fb2)[cg];
    u64 accp[4][2];
#pragma unroll
    for (int i = 0; i < 4; i++) { accp[i][0] = pk(fb.x, fb.y); accp[i][1] = pk(fb.z, fb.w); }

    const ulonglong2* sWq = (const ulonglong2*)sW;
#pragma unroll 4
    for (int kk = 0; kk < 128; kk++) {
        const float4 a = *reinterpret_cast<const float4*>(&sAT[kk*36 + 4*rg]);
        const ulonglong2 ww = sWq[kk*32 + cg];
        const float av[4] = {a.x, a.y, a.z, a.w};
#pragma unroll
        for (int i = 0; i < 4; i++) {
            const u64 aa = pk2(av[i]);
            accp[i][0] = fma2(aa, ww.x, accp[i][0]);
            accp[i][1] = fma2(aa, ww.y, accp[i][1]);
        }
    }
    float s[4] = {0,0,0,0}, sq[4] = {0,0,0,0};
#pragma unroll
    for (int i = 0; i < 4; i++) {
        const float2 lo = upk(accp[i][0]), hi = upk(accp[i][1]);
        float4 o = make_float4(lo.x, lo.y, hi.x, hi.y);
        *reinterpret_cast<float4*>(&g_lin2[(size_t)(r0 + 4*rg + i) * OUTF + 4*cg]) = o;
        s[0] += o.x; s[1] += o.y; s[2] += o.z; s[3] += o.w;
        sq[0] = fmaf(o.x,o.x,sq[0]); sq[1] = fmaf(o.y,o.y,sq[1]);
        sq[2] = fmaf(o.z,o.z,sq[2]); sq[3] = fmaf(o.w,o.w,sq[3]);
    }
#pragma unroll
    for (int qq = 0; qq < 4; qq++) { sred[rg*128 + 4*cg + qq] = s[qq]; sqred[rg*128 + 4*cg + qq] = sq[qq]; }
    __syncthreads();
    if (tid < 128) {
        float a = 0.f, v = 0.f;
#pragma unroll
        for (int r = 0; r < 8; r++) { a += sred[r*128 + tid]; v += sqred[r*128 + tid]; }
        g_part[512*256 + blockIdx.x*256 + tid]       = a;
        g_part[512*256 + blockIdx.x*256 + 128 + tid] = v;
    }
}

// ======== finalize BN coefficients (parallelized: 1024 threads) =============
__global__ __launch_bounds__(1024) void finstats_kernel(
    int sel, const float* __restrict__ gamma, const float* __restrict__ beta) {
    __shared__ float red[4*256];
    __shared__ float tot[256];
    const float* part = g_part + sel * (512*256);
    float* bn = g_bn + sel * (2*OUTF);
    const int t = threadIdx.x;
    const int c = t & 255;
    const int g = t >> 8;
    float s = 0.f;
    const int rbeg = g * 128;
#pragma unroll 4
    for (int i = 0; i < 128; i++) s += part[(rbeg + i)*256 + c];
    red[g*256 + c] = s;
    __syncthreads();
    if (t < 256) tot[t] = (red[t] + red[256 + t]) + (red[512 + t] + red[768 + t]);
    __syncthreads();
    if (t < 128) {
        const float inv_n = 1.f / (float)NROW;
        const float m  = tot[t] * inv_n;
        const float v  = tot[128 + t] * inv_n - m * m;
        const float rs = rsqrtf(v + 1e-5f);
        const float a  = rs * gamma[t];
        bn[t]       = a;
        bn[128 + t] = beta[t] - m * a;
    }
}

// ===================== K7: final BN2 -> output (vectorized) =================
__global__ __launch_bounds__(1024) void final_kernel(float* __restrict__ out) {
    const int i = blockIdx.x * 1024 + threadIdx.x;   // float4 units
    const int c0 = (i << 2) & 127;
    const float* bn = g_bn + 2*OUTF;
    const float4 v = ((const float4*)g_lin2)[i];
    float4 o;
    o.x = fmaf(v.x, bn[c0],   bn[128 + c0]);
    o.y = fmaf(v.y, bn[c0+1], bn[128 + c0 + 1]);
    o.z = fmaf(v.z, bn[c0+2], bn[128 + c0 + 2]);
    o.w = fmaf(v.w, bn[c0+3], bn[128 + c0 + 3]);
    ((float4*)out)[i] = o;
}

// ============================================================================
extern "C" void kernel_launch(void* const* d_in, const int* in_sizes, int n_in,
                              void* d_out, int out_size) {
    (void)in_sizes; (void)n_in; (void)out_size;
    const float* x   = (const float*)d_in[0];
    const float* pos = (const float*)d_in[1];
    const float* rw1 = (const float*)d_in[2];
    const float* rb1 = (const float*)d_in[3];
    const float* rw2 = (const float*)d_in[4];
    const float* rb2 = (const float*)d_in[5];
    const float* rw3 = (const float*)d_in[6];
    const float* rb3 = (const float*)d_in[7];
    const float* fw1 = (const float*)d_in[8];
    const float* fb1 = (const float*)d_in[9];
    const float* g1  = (const float*)d_in[10];
    const float* b1  = (const float*)d_in[11];
    const float* fw2 = (const float*)d_in[12];
    const float* fb2 = (const float*)d_in[13];
    const float* g2  = (const float*)d_in[14];
    const float* b2  = (const float*)d_in[15];
    float* out = (float*)d_out;

    // stage MLP weights into constant memory (D2D async copies; capturable)
    cudaMemcpyToSymbolAsync(cw1, rw1, 10*32*4,  0, cudaMemcpyDeviceToDevice);
    cudaMemcpyToSymbolAsync(cb1, rb1, 32*4,     0, cudaMemcpyDeviceToDevice);
    cudaMemcpyToSymbolAsync(cw2, rw2, 32*64*4,  0, cudaMemcpyDeviceToDevice);
    cudaMemcpyToSymbolAsync(cb2, rb2, 64*4,     0, cudaMemcpyDeviceToDevice);
    cudaMemcpyToSymbolAsync(cw3, rw3, 64*64*4,  0, cudaMemcpyDeviceToDevice);
    cudaMemcpyToSymbolAsync(cb3, rb3, 64*4,     0, cudaMemcpyDeviceToDevice);

    // 2 nops so the ncu capture (4th kernel) lands on relconv_kernel.
    nop_kernel<<<1, 32>>>();
    nop_kernel<<<1, 32>>>();

    const int smem_knn = (NPTS*3 + 2048 + 16 + 512 + 512 + 16 + 4) * 4;  // ~60.4 KB
    cudaFuncSetAttribute(knn_kernel, cudaFuncAttributeMaxDynamicSharedMemorySize, smem_knn);
    knn_kernel<<<1024, 512, smem_knn>>>(pos);

    relconv_kernel<<<NITEM/128, 128>>>(x, pos);

    const int smem1 = (8192 + 2304 + 2048) * 4;
    cudaFuncSetAttribute(gemm1_kernel, cudaFuncAttributeMaxDynamicSharedMemorySize, smem1);
    gemm1_kernel<<<NROW/32, 256, smem1>>>(fw1, fb1);
    finstats_kernel<<<1, 1024>>>(0, g1, b1);

    const int smem2 = (16384 + 4608 + 2048) * 4;
    cudaFuncSetAttribute(gemm2_kernel, cudaFuncAttributeMaxDynamicSharedMemorySize, smem2);
    gemm2_kernel<<<NROW/32, 256, smem2>>>(fw2, fb2);
    finstats_kernel<<<1, 1024>>>(1, g2, b2);

    final_kernel<<<524288/1024, 1024>>>(out);
}